// round 1
// baseline (speedup 1.0000x reference)
#include <cuda_runtime.h>
#include <cstddef>

#define NN   100000
#define FEAT 256
#define HID  128
#define NOUT 64
#define HOPS 3

// 6 work buffers: curr_s, next_s, feat_s, curr_t, next_t, feat_t
__device__ float g_work[6][(size_t)NN * HID];

// -------------------- vector atomic reduce --------------------
__device__ __forceinline__ void red_add_v4(float* addr, float4 v) {
    asm volatile("red.global.add.v4.f32 [%0], {%1, %2, %3, %4};"
                 :: "l"(addr), "f"(v.x), "f"(v.y), "f"(v.z), "f"(v.w)
                 : "memory");
}

// -------------------- input GEMM: x = A @ W + b; curr = x; feat = w0 * x ----
// A: [M, 256], W: [256, 128]. Tile: BM=64, BN=128, BK=16, 256 threads, 8x4/thread.
__global__ __launch_bounds__(256)
void gemm_input_kernel(const float* __restrict__ A, const float* __restrict__ W,
                       const float* __restrict__ bias, const float* __restrict__ whop,
                       float* __restrict__ curr, float* __restrict__ feat, int M) {
    __shared__ float As[16][64];
    __shared__ float Bs[16][128];
    int tid = threadIdx.x;
    int tx = tid & 31;          // 32 col-groups * 4 = 128 cols
    int ty = tid >> 5;          // 8 row-groups  * 8 = 64 rows
    int row0 = blockIdx.x * 64;

    float acc[8][4];
    #pragma unroll
    for (int i = 0; i < 8; i++)
        #pragma unroll
        for (int j = 0; j < 4; j++) acc[i][j] = 0.f;

    int arow = tid >> 2;            // 0..63
    int acol = (tid & 3) * 4;       // 0,4,8,12

    for (int k0 = 0; k0 < FEAT; k0 += 16) {
        float4 av = make_float4(0.f, 0.f, 0.f, 0.f);
        int gr = row0 + arow;
        if (gr < M) av = *(const float4*)(A + (size_t)gr * FEAT + k0 + acol);
        As[acol + 0][arow] = av.x;
        As[acol + 1][arow] = av.y;
        As[acol + 2][arow] = av.z;
        As[acol + 3][arow] = av.w;
        #pragma unroll
        for (int j = 0; j < 2; j++) {
            int f = tid + j * 256;            // 0..511 float4 slots
            int brow = f >> 5;
            int bcol = (f & 31) * 4;
            *(float4*)&Bs[brow][bcol] =
                *(const float4*)(W + (size_t)(k0 + brow) * HID + bcol);
        }
        __syncthreads();
        #pragma unroll
        for (int kk = 0; kk < 16; kk++) {
            float a[8], b[4];
            *(float4*)&a[0] = *(const float4*)&As[kk][ty * 8];
            *(float4*)&a[4] = *(const float4*)&As[kk][ty * 8 + 4];
            *(float4*)&b[0] = *(const float4*)&Bs[kk][tx * 4];
            #pragma unroll
            for (int i = 0; i < 8; i++)
                #pragma unroll
                for (int j = 0; j < 4; j++) acc[i][j] += a[i] * b[j];
        }
        __syncthreads();
    }

    float w0 = whop[0];
    float4 bb = *(const float4*)(bias + tx * 4);
    #pragma unroll
    for (int i = 0; i < 8; i++) {
        int r = row0 + ty * 8 + i;
        if (r < M) {
            float4 v;
            v.x = acc[i][0] + bb.x;
            v.y = acc[i][1] + bb.y;
            v.z = acc[i][2] + bb.z;
            v.w = acc[i][3] + bb.w;
            *(float4*)(curr + (size_t)r * HID + tx * 4) = v;
            float4 fv = make_float4(w0 * v.x, w0 * v.y, w0 * v.z, w0 * v.w);
            *(float4*)(feat + (size_t)r * HID + tx * 4) = fv;
        }
    }
}

// -------------------- edge pass: both directions in one sweep ---------------
// next_s[row] += w * curr_s[col]; next_t[col] += w * curr_t[row]
// one warp per edge; lane owns 4 contiguous floats of the 128-wide feature.
__global__ __launch_bounds__(256)
void edge_kernel(const int* __restrict__ erow, const int* __restrict__ ecol,
                 const float* __restrict__ ew,
                 const float* __restrict__ cs, const float* __restrict__ ct,
                 float* __restrict__ ns, float* __restrict__ nt, int E) {
    int lane = threadIdx.x & 31;
    int warp = (int)((blockIdx.x * blockDim.x + threadIdx.x) >> 5);
    int nwarps = (int)((gridDim.x * blockDim.x) >> 5);
    for (int e = warp; e < E; e += nwarps) {
        int r = __ldcs(erow + e);
        int c = __ldcs(ecol + e);
        float w = __ldcs(ew + e);
        float4 vs = *((const float4*)(cs + (size_t)c * HID) + lane);
        float4 vt = *((const float4*)(ct + (size_t)r * HID) + lane);
        float4 os = make_float4(w * vs.x, w * vs.y, w * vs.z, w * vs.w);
        float4 ot = make_float4(w * vt.x, w * vt.y, w * vt.z, w * vt.w);
        red_add_v4(ns + (size_t)r * HID + lane * 4, os);
        red_add_v4(nt + (size_t)c * HID + lane * 4, ot);
    }
}

// -------------------- feat accumulate: feat += w[h] * next ------------------
__global__ __launch_bounds__(256)
void axpy_kernel(float* __restrict__ fs, const float* __restrict__ ns,
                 float* __restrict__ ft, const float* __restrict__ nt,
                 const float* __restrict__ ws, const float* __restrict__ wt,
                 int h, int n4) {
    float a = ws[h];
    float b = wt[h];
    int stride = gridDim.x * blockDim.x;
    for (int i = blockIdx.x * blockDim.x + threadIdx.x; i < n4; i += stride) {
        float4 f = ((float4*)fs)[i];
        float4 n = ((const float4*)ns)[i];
        f.x += a * n.x; f.y += a * n.y; f.z += a * n.z; f.w += a * n.w;
        ((float4*)fs)[i] = f;
        float4 g = ((float4*)ft)[i];
        float4 m = ((const float4*)nt)[i];
        g.x += b * m.x; g.y += b * m.y; g.z += b * m.z; g.w += b * m.w;
        ((float4*)ft)[i] = g;
    }
}

// -------------------- output GEMM: out = [fs|ft] @ W_node + b_node ----------
// A: [M, 256] (concat of two [M,128]), W: [256, 64]. BM=64, BN=64, BK=16,
// 256 threads, 4x4 per thread.
__global__ __launch_bounds__(256)
void gemm_out_kernel(const float* __restrict__ fs, const float* __restrict__ ft,
                     const float* __restrict__ Wn, const float* __restrict__ bn,
                     float* __restrict__ out, int M) {
    __shared__ float As[16][64];
    __shared__ float Bs[16][64];
    int tid = threadIdx.x;
    int tx = tid & 15;          // 16 col-groups * 4 = 64 cols
    int ty = tid >> 4;          // 16 row-groups * 4 = 64 rows
    int row0 = blockIdx.x * 64;

    float acc[4][4];
    #pragma unroll
    for (int i = 0; i < 4; i++)
        #pragma unroll
        for (int j = 0; j < 4; j++) acc[i][j] = 0.f;

    int arow = tid >> 2;
    int acol = (tid & 3) * 4;

    for (int k0 = 0; k0 < 2 * HID; k0 += 16) {
        const float* A = (k0 < HID) ? fs : ft;
        int kc = k0 & (HID - 1);
        float4 av = make_float4(0.f, 0.f, 0.f, 0.f);
        int gr = row0 + arow;
        if (gr < M) av = *(const float4*)(A + (size_t)gr * HID + kc + acol);
        As[acol + 0][arow] = av.x;
        As[acol + 1][arow] = av.y;
        As[acol + 2][arow] = av.z;
        As[acol + 3][arow] = av.w;
        {
            int brow = tid >> 4;           // 0..15
            int bcol = (tid & 15) * 4;     // 0..60
            *(float4*)&Bs[brow][bcol] =
                *(const float4*)(Wn + (size_t)(k0 + brow) * NOUT + bcol);
        }
        __syncthreads();
        #pragma unroll
        for (int kk = 0; kk < 16; kk++) {
            float a[4], b[4];
            *(float4*)&a[0] = *(const float4*)&As[kk][ty * 4];
            *(float4*)&b[0] = *(const float4*)&Bs[kk][tx * 4];
            #pragma unroll
            for (int i = 0; i < 4; i++)
                #pragma unroll
                for (int j = 0; j < 4; j++) acc[i][j] += a[i] * b[j];
        }
        __syncthreads();
    }

    float4 bb = *(const float4*)(bn + tx * 4);
    #pragma unroll
    for (int i = 0; i < 4; i++) {
        int r = row0 + ty * 4 + i;
        if (r < M) {
            float4 v;
            v.x = acc[i][0] + bb.x;
            v.y = acc[i][1] + bb.y;
            v.z = acc[i][2] + bb.z;
            v.w = acc[i][3] + bb.w;
            *(float4*)(out + (size_t)r * NOUT + tx * 4) = v;
        }
    }
}

// ---------------------------------------------------------------------------
extern "C" void kernel_launch(void* const* d_in, const int* in_sizes, int n_in,
                              void* d_out, int out_size) {
    const float* fsrc  = (const float*)d_in[0];
    const float* ftgt  = (const float*)d_in[1];
    const int*   erow  = (const int*)d_in[2];
    const int*   ecol  = (const int*)d_in[3];
    const float* ew    = (const float*)d_in[4];
    const float* W_src = (const float*)d_in[5];
    const float* b_src = (const float*)d_in[6];
    const float* W_tgt = (const float*)d_in[7];
    const float* b_tgt = (const float*)d_in[8];
    const float* w_s   = (const float*)d_in[9];
    const float* w_t   = (const float*)d_in[10];
    const float* W_nd  = (const float*)d_in[11];
    const float* b_nd  = (const float*)d_in[12];
    float* out = (float*)d_out;

    int M = in_sizes[0] / FEAT;
    int E = in_sizes[2];
    size_t nh = (size_t)M * HID;

    float* base;
    cudaGetSymbolAddress((void**)&base, g_work);
    size_t cap = (size_t)NN * HID;
    float* cs = base + 0 * cap;
    float* ns = base + 1 * cap;
    float* fs = base + 2 * cap;
    float* ct = base + 3 * cap;
    float* nt = base + 4 * cap;
    float* ft = base + 5 * cap;

    int gblocks = (M + 63) / 64;
    gemm_input_kernel<<<gblocks, 256>>>(fsrc, W_src, b_src, w_s, cs, fs, M);
    gemm_input_kernel<<<gblocks, 256>>>(ftgt, W_tgt, b_tgt, w_t, ct, ft, M);

    int n4 = (int)(nh / 4);
    for (int h = 1; h <= HOPS; h++) {
        cudaMemsetAsync(ns, 0, nh * sizeof(float));
        cudaMemsetAsync(nt, 0, nh * sizeof(float));
        edge_kernel<<<4096, 256>>>(erow, ecol, ew, cs, ct, ns, nt, E);
        axpy_kernel<<<2048, 256>>>(fs, ns, ft, nt, w_s, w_t, h, n4);
        float* tmp;
        tmp = cs; cs = ns; ns = tmp;
        tmp = ct; ct = nt; nt = tmp;
    }

    gemm_out_kernel<<<gblocks, 256>>>(fs, ft, W_nd, b_nd, out, M);
}

// round 2
// speedup vs baseline: 2.6089x; 2.6089x over previous
#include <cuda_runtime.h>
#include <cstddef>

#define NN    100000
#define NEDGE 3200000
#define FEAT  256
#define HID   128
#define NOUT  64
#define HOPS  3

// 6 work buffers: curr_s, next_s, feat_s, curr_t, next_t, feat_t
__device__ float g_work[6][(size_t)NN * HID];
__device__ int   g_deg[2][NN];
__device__ int   g_rowptr[2][NN + 1];
__device__ int   g_fill[2][NN];
__device__ int   g_bsum[2][128];
__device__ int2  g_csr[2][NEDGE];

// ======================= CSR build =======================
__global__ __launch_bounds__(256)
void hist_kernel(const int* __restrict__ erow, const int* __restrict__ ecol,
                 int* __restrict__ deg_s, int* __restrict__ deg_t, int E) {
    int e = blockIdx.x * blockDim.x + threadIdx.x;
    if (e < E) {
        atomicAdd(&deg_s[erow[e]], 1);
        atomicAdd(&deg_t[ecol[e]], 1);
    }
}

// inclusive scan of 1024-chunks -> exclusive within chunk + chunk totals
__global__ __launch_bounds__(1024)
void scan_chunk(const int* __restrict__ in, int* __restrict__ out,
                int* __restrict__ bsum, int n) {
    __shared__ int sh[1024];
    int t = threadIdx.x;
    int g = blockIdx.x * 1024 + t;
    int v = (g < n) ? in[g] : 0;
    sh[t] = v;
    __syncthreads();
    #pragma unroll
    for (int off = 1; off < 1024; off <<= 1) {
        int x = (t >= off) ? sh[t - off] : 0;
        __syncthreads();
        sh[t] += x;
        __syncthreads();
    }
    if (g < n) out[g] = sh[t] - v;         // exclusive within chunk
    if (t == 1023) bsum[blockIdx.x] = sh[1023];
}

__global__ void scan_block_sums(int* bsum, int nb) {
    if (threadIdx.x == 0 && blockIdx.x == 0) {
        int s = 0;
        for (int i = 0; i < nb; i++) { int v = bsum[i]; bsum[i] = s; s += v; }
    }
}

__global__ __launch_bounds__(256)
void scan_finalize(int* __restrict__ rowptr, const int* __restrict__ boff,
                   int* __restrict__ fill, int n, int total) {
    int g = blockIdx.x * blockDim.x + threadIdx.x;
    if (g < n) {
        int v = rowptr[g] + boff[g >> 10];
        rowptr[g] = v;
        fill[g] = v;
    }
    if (g == n) rowptr[n] = total;
}

__global__ __launch_bounds__(256)
void scatter_kernel(const int* __restrict__ erow, const int* __restrict__ ecol,
                    const float* __restrict__ ew,
                    int* __restrict__ fill_s, int* __restrict__ fill_t,
                    int2* __restrict__ csr_s, int2* __restrict__ csr_t, int E) {
    int e = blockIdx.x * blockDim.x + threadIdx.x;
    if (e >= E) return;
    int r = erow[e];
    int c = ecol[e];
    int wb = __float_as_int(ew[e]);
    int ps = atomicAdd(&fill_s[r], 1);
    csr_s[ps] = make_int2(c, wb);
    int pt = atomicAdd(&fill_t[c], 1);
    csr_t[pt] = make_int2(r, wb);
}

// ======================= SPMM: warp per node, fused feat update =============
// next[i] = sum_e w_e * x[nbr_e];  feat[i] += whop[h] * next[i]
__global__ __launch_bounds__(256)
void spmm_kernel(const int* __restrict__ rowptr, const int2* __restrict__ csr,
                 const float* __restrict__ x, float* __restrict__ next,
                 float* __restrict__ feat, const float* __restrict__ whop,
                 int h, int n) {
    int lane = threadIdx.x & 31;
    int node = (int)((blockIdx.x * blockDim.x + threadIdx.x) >> 5);
    if (node >= n) return;
    int beg = rowptr[node];
    int end = rowptr[node + 1];
    float4 acc = make_float4(0.f, 0.f, 0.f, 0.f);

    int p = beg;
    for (; p + 32 <= end; p += 32) {
        int2 ed = csr[p + lane];
        #pragma unroll
        for (int j = 0; j < 32; j++) {
            int   c  = __shfl_sync(0xffffffffu, ed.x, j);
            float wv = __int_as_float(__shfl_sync(0xffffffffu, ed.y, j));
            float4 v = *((const float4*)(x + (size_t)c * HID) + lane);
            acc.x += wv * v.x; acc.y += wv * v.y;
            acc.z += wv * v.z; acc.w += wv * v.w;
        }
    }
    int rem = end - p;
    if (rem > 0) {
        int2 ed = (lane < rem) ? csr[p + lane] : make_int2(0, 0);
        for (int j = 0; j < rem; j++) {
            int   c  = __shfl_sync(0xffffffffu, ed.x, j);
            float wv = __int_as_float(__shfl_sync(0xffffffffu, ed.y, j));
            float4 v = *((const float4*)(x + (size_t)c * HID) + lane);
            acc.x += wv * v.x; acc.y += wv * v.y;
            acc.z += wv * v.z; acc.w += wv * v.w;
        }
    }

    float wh = whop[h];
    *((float4*)(next + (size_t)node * HID) + lane) = acc;
    float4* fp = (float4*)(feat + (size_t)node * HID) + lane;
    float4 f = *fp;
    f.x += wh * acc.x; f.y += wh * acc.y;
    f.z += wh * acc.z; f.w += wh * acc.w;
    *fp = f;
}

// ======================= input GEMM: 128x128 tile, 8x8 microtile ============
// x = A @ W + b ; curr = x ; feat = w0 * x.  A:[M,256], W:[256,128]
__global__ __launch_bounds__(256)
void gemm_input_kernel(const float* __restrict__ A, const float* __restrict__ W,
                       const float* __restrict__ bias, const float* __restrict__ whop,
                       float* __restrict__ curr, float* __restrict__ feat, int M) {
    __shared__ float As[8][128];
    __shared__ float Bs[8][128];
    int tid = threadIdx.x;
    int row0 = blockIdx.x * 128;
    int arow = tid >> 1;          // 0..127
    int acol = (tid & 1) * 4;     // 0 or 4
    int brow = tid >> 5;          // 0..7
    int bcol = (tid & 31) * 4;    // 0..124
    int ty = tid >> 4;            // 0..15 -> rows ty*8..
    int tx = tid & 15;            // 0..15 -> cols tx*8..

    float acc[8][8];
    #pragma unroll
    for (int i = 0; i < 8; i++)
        #pragma unroll
        for (int j = 0; j < 8; j++) acc[i][j] = 0.f;

    for (int k0 = 0; k0 < FEAT; k0 += 8) {
        float4 av = make_float4(0.f, 0.f, 0.f, 0.f);
        int gr = row0 + arow;
        if (gr < M) av = *(const float4*)(A + (size_t)gr * FEAT + k0 + acol);
        As[acol + 0][arow] = av.x;
        As[acol + 1][arow] = av.y;
        As[acol + 2][arow] = av.z;
        As[acol + 3][arow] = av.w;
        *(float4*)&Bs[brow][bcol] =
            *(const float4*)(W + (size_t)(k0 + brow) * HID + bcol);
        __syncthreads();
        #pragma unroll
        for (int kk = 0; kk < 8; kk++) {
            float a[8], b[8];
            *(float4*)&a[0] = *(const float4*)&As[kk][ty * 8];
            *(float4*)&a[4] = *(const float4*)&As[kk][ty * 8 + 4];
            *(float4*)&b[0] = *(const float4*)&Bs[kk][tx * 8];
            *(float4*)&b[4] = *(const float4*)&Bs[kk][tx * 8 + 4];
            #pragma unroll
            for (int i = 0; i < 8; i++)
                #pragma unroll
                for (int j = 0; j < 8; j++) acc[i][j] += a[i] * b[j];
        }
        __syncthreads();
    }

    float w0 = whop[0];
    float bb[8];
    *(float4*)&bb[0] = *(const float4*)(bias + tx * 8);
    *(float4*)&bb[4] = *(const float4*)(bias + tx * 8 + 4);
    #pragma unroll
    for (int i = 0; i < 8; i++) {
        int r = row0 + ty * 8 + i;
        if (r < M) {
            float v[8];
            #pragma unroll
            for (int j = 0; j < 8; j++) v[j] = acc[i][j] + bb[j];
            *(float4*)(curr + (size_t)r * HID + tx * 8)     = *(float4*)&v[0];
            *(float4*)(curr + (size_t)r * HID + tx * 8 + 4) = *(float4*)&v[4];
            float fv[8];
            #pragma unroll
            for (int j = 0; j < 8; j++) fv[j] = w0 * v[j];
            *(float4*)(feat + (size_t)r * HID + tx * 8)     = *(float4*)&fv[0];
            *(float4*)(feat + (size_t)r * HID + tx * 8 + 4) = *(float4*)&fv[4];
        }
    }
}

// ======================= output GEMM: out = [fs|ft] @ W_node + b ============
__global__ __launch_bounds__(256)
void gemm_out_kernel(const float* __restrict__ fs, const float* __restrict__ ft,
                     const float* __restrict__ Wn, const float* __restrict__ bn,
                     float* __restrict__ out, int M) {
    __shared__ float As[16][64];
    __shared__ float Bs[16][64];
    int tid = threadIdx.x;
    int tx = tid & 15;
    int ty = tid >> 4;
    int row0 = blockIdx.x * 64;

    float acc[4][4];
    #pragma unroll
    for (int i = 0; i < 4; i++)
        #pragma unroll
        for (int j = 0; j < 4; j++) acc[i][j] = 0.f;

    int arow = tid >> 2;
    int acol = (tid & 3) * 4;

    for (int k0 = 0; k0 < 2 * HID; k0 += 16) {
        const float* A = (k0 < HID) ? fs : ft;
        int kc = k0 & (HID - 1);
        float4 av = make_float4(0.f, 0.f, 0.f, 0.f);
        int gr = row0 + arow;
        if (gr < M) av = *(const float4*)(A + (size_t)gr * HID + kc + acol);
        As[acol + 0][arow] = av.x;
        As[acol + 1][arow] = av.y;
        As[acol + 2][arow] = av.z;
        As[acol + 3][arow] = av.w;
        {
            int brow = tid >> 4;
            int bcol = (tid & 15) * 4;
            *(float4*)&Bs[brow][bcol] =
                *(const float4*)(Wn + (size_t)(k0 + brow) * NOUT + bcol);
        }
        __syncthreads();
        #pragma unroll
        for (int kk = 0; kk < 16; kk++) {
            float a[4], b[4];
            *(float4*)&a[0] = *(const float4*)&As[kk][ty * 4];
            *(float4*)&b[0] = *(const float4*)&Bs[kk][tx * 4];
            #pragma unroll
            for (int i = 0; i < 4; i++)
                #pragma unroll
                for (int j = 0; j < 4; j++) acc[i][j] += a[i] * b[j];
        }
        __syncthreads();
    }

    float4 bb = *(const float4*)(bn + tx * 4);
    #pragma unroll
    for (int i = 0; i < 4; i++) {
        int r = row0 + ty * 4 + i;
        if (r < M) {
            float4 v;
            v.x = acc[i][0] + bb.x;
            v.y = acc[i][1] + bb.y;
            v.z = acc[i][2] + bb.z;
            v.w = acc[i][3] + bb.w;
            *(float4*)(out + (size_t)r * NOUT + tx * 4) = v;
        }
    }
}

// ===========================================================================
extern "C" void kernel_launch(void* const* d_in, const int* in_sizes, int n_in,
                              void* d_out, int out_size) {
    const float* fsrc  = (const float*)d_in[0];
    const float* ftgt  = (const float*)d_in[1];
    const int*   erow  = (const int*)d_in[2];
    const int*   ecol  = (const int*)d_in[3];
    const float* ew    = (const float*)d_in[4];
    const float* W_src = (const float*)d_in[5];
    const float* b_src = (const float*)d_in[6];
    const float* W_tgt = (const float*)d_in[7];
    const float* b_tgt = (const float*)d_in[8];
    const float* w_s   = (const float*)d_in[9];
    const float* w_t   = (const float*)d_in[10];
    const float* W_nd  = (const float*)d_in[11];
    const float* b_nd  = (const float*)d_in[12];
    float* out = (float*)d_out;

    int M = in_sizes[0] / FEAT;
    int E = in_sizes[2];

    float* wbase;  cudaGetSymbolAddress((void**)&wbase, g_work);
    int*   deg;    cudaGetSymbolAddress((void**)&deg, g_deg);
    int*   rowptr; cudaGetSymbolAddress((void**)&rowptr, g_rowptr);
    int*   fill;   cudaGetSymbolAddress((void**)&fill, g_fill);
    int*   bsum;   cudaGetSymbolAddress((void**)&bsum, g_bsum);
    int2*  csr;    cudaGetSymbolAddress((void**)&csr, g_csr);

    size_t cap = (size_t)NN * HID;
    float* cs = wbase + 0 * cap;
    float* ns = wbase + 1 * cap;
    float* fs = wbase + 2 * cap;
    float* ct = wbase + 3 * cap;
    float* nt = wbase + 4 * cap;
    float* ft = wbase + 5 * cap;

    int* deg_s = deg;            int* deg_t = deg + NN;
    int* rp_s  = rowptr;         int* rp_t  = rowptr + (NN + 1);
    int* fil_s = fill;           int* fil_t = fill + NN;
    int* bs_s  = bsum;           int* bs_t  = bsum + 128;
    int2* csr_s = csr;           int2* csr_t = csr + NEDGE;

    int eblocks = (E + 255) / 256;
    int nchunks = (M + 1023) / 1024;

    // ---- CSR build (both directions) ----
    cudaMemsetAsync(deg_s, 0, 2 * NN * sizeof(int));
    hist_kernel<<<eblocks, 256>>>(erow, ecol, deg_s, deg_t, E);
    scan_chunk<<<nchunks, 1024>>>(deg_s, rp_s, bs_s, M);
    scan_chunk<<<nchunks, 1024>>>(deg_t, rp_t, bs_t, M);
    scan_block_sums<<<1, 32>>>(bs_s, nchunks);
    scan_block_sums<<<1, 32>>>(bs_t, nchunks);
    scan_finalize<<<(M + 256) / 256, 256>>>(rp_s, bs_s, fil_s, M, E);
    scan_finalize<<<(M + 256) / 256, 256>>>(rp_t, bs_t, fil_t, M, E);
    scatter_kernel<<<eblocks, 256>>>(erow, ecol, ew, fil_s, fil_t, csr_s, csr_t, E);

    // ---- input projections ----
    int gblocks = (M + 127) / 128;
    gemm_input_kernel<<<gblocks, 256>>>(fsrc, W_src, b_src, w_s, cs, fs, M);
    gemm_input_kernel<<<gblocks, 256>>>(ftgt, W_tgt, b_tgt, w_t, ct, ft, M);

    // ---- hops ----
    int sblocks = (M * 32 + 255) / 256;   // warp per node
    for (int h = 1; h <= HOPS; h++) {
        spmm_kernel<<<sblocks, 256>>>(rp_s, csr_s, cs, ns, fs, w_s, h, M);
        spmm_kernel<<<sblocks, 256>>>(rp_t, csr_t, ct, nt, ft, w_t, h, M);
        float* tmp;
        tmp = cs; cs = ns; ns = tmp;
        tmp = ct; ct = nt; nt = tmp;
    }

    // ---- output projection ----
    gemm_out_kernel<<<(M + 63) / 64, 256>>>(fs, ft, W_nd, b_nd, out, M);
}

// round 3
// speedup vs baseline: 3.2622x; 1.2504x over previous
#include <cuda_runtime.h>
#include <cuda_fp16.h>
#include <cstddef>

#define NN    100000
#define NEDGE 3200000
#define FEAT  256
#define HID   128
#define NOUT  64
#define HOPS  3

// fp16 hop buffers: curr_s, next_s, curr_t, next_t
__device__ __half g_hbuf[4][(size_t)NN * HID];
// fp32 feat accumulators: feat_s, feat_t
__device__ float  g_feat[2][(size_t)NN * HID];
__device__ int    g_deg[2][NN];
__device__ int    g_rowptr[2][NN + 1];
__device__ int    g_fill[2][NN];
__device__ int    g_bsum[2][128];
__device__ int2   g_csr[2][NEDGE];

// ======================= CSR build =======================
__global__ __launch_bounds__(256)
void hist_kernel(const int* __restrict__ erow, const int* __restrict__ ecol,
                 int* __restrict__ deg_s, int* __restrict__ deg_t, int E) {
    int e = blockIdx.x * blockDim.x + threadIdx.x;
    if (e < E) {
        atomicAdd(&deg_s[erow[e]], 1);
        atomicAdd(&deg_t[ecol[e]], 1);
    }
}

__global__ __launch_bounds__(1024)
void scan_chunk(const int* __restrict__ in, int* __restrict__ out,
                int* __restrict__ bsum, int n) {
    __shared__ int sh[1024];
    int t = threadIdx.x;
    int g = blockIdx.x * 1024 + t;
    int v = (g < n) ? in[g] : 0;
    sh[t] = v;
    __syncthreads();
    #pragma unroll
    for (int off = 1; off < 1024; off <<= 1) {
        int x = (t >= off) ? sh[t - off] : 0;
        __syncthreads();
        sh[t] += x;
        __syncthreads();
    }
    if (g < n) out[g] = sh[t] - v;         // exclusive within chunk
    if (t == 1023) bsum[blockIdx.x] = sh[1023];
}

// both directions in one launch (block 0 -> s, block 1 -> t)
__global__ void scan_block_sums2(int* bsum_s, int* bsum_t, int nb) {
    if (threadIdx.x == 0) {
        int* b = blockIdx.x ? bsum_t : bsum_s;
        int s = 0;
        for (int i = 0; i < nb; i++) { int v = b[i]; b[i] = s; s += v; }
    }
}

__global__ __launch_bounds__(256)
void scan_finalize(int* __restrict__ rowptr, const int* __restrict__ boff,
                   int* __restrict__ fill, int n, int total) {
    int g = blockIdx.x * blockDim.x + threadIdx.x;
    if (g < n) {
        int v = rowptr[g] + boff[g >> 10];
        rowptr[g] = v;
        fill[g] = v;
    }
    if (g == n) rowptr[n] = total;
}

__global__ __launch_bounds__(256)
void scatter_kernel(const int* __restrict__ erow, const int* __restrict__ ecol,
                    const float* __restrict__ ew,
                    int* __restrict__ fill_s, int* __restrict__ fill_t,
                    int2* __restrict__ csr_s, int2* __restrict__ csr_t, int E) {
    int e = blockIdx.x * blockDim.x + threadIdx.x;
    if (e >= E) return;
    int r = erow[e];
    int c = ecol[e];
    int wb = __float_as_int(ew[e]);
    int ps = atomicAdd(&fill_s[r], 1);
    csr_s[ps] = make_int2(c, wb);
    int pt = atomicAdd(&fill_t[c], 1);
    csr_t[pt] = make_int2(r, wb);
}

// ======================= SPMM (fp16 gather, fp32 accumulate) ================
// next[i] = fp16( sum_e w_e * x[nbr_e] );  feat[i] += whop[h] * sum (fp32)
// warp per node; lane owns 4 consecutive halves (8 bytes) of the 128-wide row.
__global__ __launch_bounds__(256)
void spmm_kernel(const int* __restrict__ rowptr, const int2* __restrict__ csr,
                 const __half* __restrict__ x, __half* __restrict__ next,
                 float* __restrict__ feat, const float* __restrict__ whop,
                 int h, int n) {
    int lane = threadIdx.x & 31;
    int node = (int)((blockIdx.x * blockDim.x + threadIdx.x) >> 5);
    if (node >= n) return;
    int beg = rowptr[node];
    int end = rowptr[node + 1];
    float4 acc = make_float4(0.f, 0.f, 0.f, 0.f);

    int p = beg;
    for (; p + 32 <= end; p += 32) {
        int2 ed = csr[p + lane];
        #pragma unroll
        for (int j = 0; j < 32; j++) {
            int   c  = __shfl_sync(0xffffffffu, ed.x, j);
            float wv = __int_as_float(__shfl_sync(0xffffffffu, ed.y, j));
            __half2 h2[2];
            *(uint2*)h2 = *((const uint2*)(x + (size_t)c * HID) + lane);
            float2 v0 = __half22float2(h2[0]);
            float2 v1 = __half22float2(h2[1]);
            acc.x += wv * v0.x; acc.y += wv * v0.y;
            acc.z += wv * v1.x; acc.w += wv * v1.y;
        }
    }
    int rem = end - p;
    if (rem > 0) {
        int2 ed = (lane < rem) ? csr[p + lane] : make_int2(0, 0);
        for (int j = 0; j < rem; j++) {
            int   c  = __shfl_sync(0xffffffffu, ed.x, j);
            float wv = __int_as_float(__shfl_sync(0xffffffffu, ed.y, j));
            __half2 h2[2];
            *(uint2*)h2 = *((const uint2*)(x + (size_t)c * HID) + lane);
            float2 v0 = __half22float2(h2[0]);
            float2 v1 = __half22float2(h2[1]);
            acc.x += wv * v0.x; acc.y += wv * v0.y;
            acc.z += wv * v1.x; acc.w += wv * v1.y;
        }
    }

    // write next as fp16
    __half2 o2[2];
    o2[0] = __floats2half2_rn(acc.x, acc.y);
    o2[1] = __floats2half2_rn(acc.z, acc.w);
    *((uint2*)(next + (size_t)node * HID) + lane) = *(uint2*)o2;

    // fp32 feat update
    float wh = whop[h];
    float4* fp = (float4*)(feat + (size_t)node * HID) + lane;
    float4 f = *fp;
    f.x += wh * acc.x; f.y += wh * acc.y;
    f.z += wh * acc.z; f.w += wh * acc.w;
    *fp = f;
}

// ======================= input GEMM: 128x128 tile, 8x8 microtile ============
// x = A @ W + b ; curr = fp16(x) ; feat = w0 * x (fp32).  A:[M,256], W:[256,128]
__global__ __launch_bounds__(256)
void gemm_input_kernel(const float* __restrict__ A, const float* __restrict__ W,
                       const float* __restrict__ bias, const float* __restrict__ whop,
                       __half* __restrict__ curr, float* __restrict__ feat, int M) {
    __shared__ float As[8][128];
    __shared__ float Bs[8][128];
    int tid = threadIdx.x;
    int row0 = blockIdx.x * 128;
    int arow = tid >> 1;          // 0..127
    int acol = (tid & 1) * 4;     // 0 or 4
    int brow = tid >> 5;          // 0..7
    int bcol = (tid & 31) * 4;    // 0..124
    int ty = tid >> 4;            // 0..15 -> rows ty*8..
    int tx = tid & 15;            // 0..15 -> cols tx*8..

    float acc[8][8];
    #pragma unroll
    for (int i = 0; i < 8; i++)
        #pragma unroll
        for (int j = 0; j < 8; j++) acc[i][j] = 0.f;

    for (int k0 = 0; k0 < FEAT; k0 += 8) {
        float4 av = make_float4(0.f, 0.f, 0.f, 0.f);
        int gr = row0 + arow;
        if (gr < M) av = *(const float4*)(A + (size_t)gr * FEAT + k0 + acol);
        As[acol + 0][arow] = av.x;
        As[acol + 1][arow] = av.y;
        As[acol + 2][arow] = av.z;
        As[acol + 3][arow] = av.w;
        *(float4*)&Bs[brow][bcol] =
            *(const float4*)(W + (size_t)(k0 + brow) * HID + bcol);
        __syncthreads();
        #pragma unroll
        for (int kk = 0; kk < 8; kk++) {
            float a[8], b[8];
            *(float4*)&a[0] = *(const float4*)&As[kk][ty * 8];
            *(float4*)&a[4] = *(const float4*)&As[kk][ty * 8 + 4];
            *(float4*)&b[0] = *(const float4*)&Bs[kk][tx * 8];
            *(float4*)&b[4] = *(const float4*)&Bs[kk][tx * 8 + 4];
            #pragma unroll
            for (int i = 0; i < 8; i++)
                #pragma unroll
                for (int j = 0; j < 8; j++) acc[i][j] += a[i] * b[j];
        }
        __syncthreads();
    }

    float w0 = whop[0];
    float bb[8];
    *(float4*)&bb[0] = *(const float4*)(bias + tx * 8);
    *(float4*)&bb[4] = *(const float4*)(bias + tx * 8 + 4);
    #pragma unroll
    for (int i = 0; i < 8; i++) {
        int r = row0 + ty * 8 + i;
        if (r < M) {
            float v[8];
            #pragma unroll
            for (int j = 0; j < 8; j++) v[j] = acc[i][j] + bb[j];
            // curr as fp16 (one 16B store)
            __half2 h2[4];
            #pragma unroll
            for (int j = 0; j < 4; j++)
                h2[j] = __floats2half2_rn(v[2 * j], v[2 * j + 1]);
            *(uint4*)(curr + (size_t)r * HID + tx * 8) = *(uint4*)h2;
            // feat fp32
            float fv[8];
            #pragma unroll
            for (int j = 0; j < 8; j++) fv[j] = w0 * v[j];
            *(float4*)(feat + (size_t)r * HID + tx * 8)     = *(float4*)&fv[0];
            *(float4*)(feat + (size_t)r * HID + tx * 8 + 4) = *(float4*)&fv[4];
        }
    }
}

// ======================= output GEMM: out = [fs|ft] @ W_node + b ============
__global__ __launch_bounds__(256)
void gemm_out_kernel(const float* __restrict__ fs, const float* __restrict__ ft,
                     const float* __restrict__ Wn, const float* __restrict__ bn,
                     float* __restrict__ out, int M) {
    __shared__ float As[16][64];
    __shared__ float Bs[16][64];
    int tid = threadIdx.x;
    int tx = tid & 15;
    int ty = tid >> 4;
    int row0 = blockIdx.x * 64;

    float acc[4][4];
    #pragma unroll
    for (int i = 0; i < 4; i++)
        #pragma unroll
        for (int j = 0; j < 4; j++) acc[i][j] = 0.f;

    int arow = tid >> 2;
    int acol = (tid & 3) * 4;

    for (int k0 = 0; k0 < 2 * HID; k0 += 16) {
        const float* A = (k0 < HID) ? fs : ft;
        int kc = k0 & (HID - 1);
        float4 av = make_float4(0.f, 0.f, 0.f, 0.f);
        int gr = row0 + arow;
        if (gr < M) av = *(const float4*)(A + (size_t)gr * HID + kc + acol);
        As[acol + 0][arow] = av.x;
        As[acol + 1][arow] = av.y;
        As[acol + 2][arow] = av.z;
        As[acol + 3][arow] = av.w;
        {
            int brow = tid >> 4;
            int bcol = (tid & 15) * 4;
            *(float4*)&Bs[brow][bcol] =
                *(const float4*)(Wn + (size_t)(k0 + brow) * NOUT + bcol);
        }
        __syncthreads();
        #pragma unroll
        for (int kk = 0; kk < 16; kk++) {
            float a[4], b[4];
            *(float4*)&a[0] = *(const float4*)&As[kk][ty * 4];
            *(float4*)&b[0] = *(const float4*)&Bs[kk][tx * 4];
            #pragma unroll
            for (int i = 0; i < 4; i++)
                #pragma unroll
                for (int j = 0; j < 4; j++) acc[i][j] += a[i] * b[j];
        }
        __syncthreads();
    }

    float4 bb = *(const float4*)(bn + tx * 4);
    #pragma unroll
    for (int i = 0; i < 4; i++) {
        int r = row0 + ty * 4 + i;
        if (r < M) {
            float4 v;
            v.x = acc[i][0] + bb.x;
            v.y = acc[i][1] + bb.y;
            v.z = acc[i][2] + bb.z;
            v.w = acc[i][3] + bb.w;
            *(float4*)(out + (size_t)r * NOUT + tx * 4) = v;
        }
    }
}

// ===========================================================================
extern "C" void kernel_launch(void* const* d_in, const int* in_sizes, int n_in,
                              void* d_out, int out_size) {
    const float* fsrc  = (const float*)d_in[0];
    const float* ftgt  = (const float*)d_in[1];
    const int*   erow  = (const int*)d_in[2];
    const int*   ecol  = (const int*)d_in[3];
    const float* ew    = (const float*)d_in[4];
    const float* W_src = (const float*)d_in[5];
    const float* b_src = (const float*)d_in[6];
    const float* W_tgt = (const float*)d_in[7];
    const float* b_tgt = (const float*)d_in[8];
    const float* w_s   = (const float*)d_in[9];
    const float* w_t   = (const float*)d_in[10];
    const float* W_nd  = (const float*)d_in[11];
    const float* b_nd  = (const float*)d_in[12];
    float* out = (float*)d_out;

    int M = in_sizes[0] / FEAT;
    int E = in_sizes[2];

    __half* hbase;  cudaGetSymbolAddress((void**)&hbase, g_hbuf);
    float*  fbase;  cudaGetSymbolAddress((void**)&fbase, g_feat);
    int*    deg;    cudaGetSymbolAddress((void**)&deg, g_deg);
    int*    rowptr; cudaGetSymbolAddress((void**)&rowptr, g_rowptr);
    int*    fill;   cudaGetSymbolAddress((void**)&fill, g_fill);
    int*    bsum;   cudaGetSymbolAddress((void**)&bsum, g_bsum);
    int2*   csr;    cudaGetSymbolAddress((void**)&csr, g_csr);

    size_t cap = (size_t)NN * HID;
    __half* cs = hbase + 0 * cap;
    __half* ns = hbase + 1 * cap;
    __half* ct = hbase + 2 * cap;
    __half* nt = hbase + 3 * cap;
    float*  fs = fbase + 0 * cap;
    float*  ft = fbase + 1 * cap;

    int* deg_s = deg;            int* deg_t = deg + NN;
    int* rp_s  = rowptr;         int* rp_t  = rowptr + (NN + 1);
    int* fil_s = fill;           int* fil_t = fill + NN;
    int* bs_s  = bsum;           int* bs_t  = bsum + 128;
    int2* csr_s = csr;           int2* csr_t = csr + NEDGE;

    int eblocks = (E + 255) / 256;
    int nchunks = (M + 1023) / 1024;

    // ---- CSR build (both directions) ----
    cudaMemsetAsync(deg_s, 0, 2 * NN * sizeof(int));
    hist_kernel<<<eblocks, 256>>>(erow, ecol, deg_s, deg_t, E);
    scan_chunk<<<nchunks, 1024>>>(deg_s, rp_s, bs_s, M);
    scan_chunk<<<nchunks, 1024>>>(deg_t, rp_t, bs_t, M);
    scan_block_sums2<<<2, 32>>>(bs_s, bs_t, nchunks);
    scan_finalize<<<(M + 256) / 256, 256>>>(rp_s, bs_s, fil_s, M, E);
    scan_finalize<<<(M + 256) / 256, 256>>>(rp_t, bs_t, fil_t, M, E);
    scatter_kernel<<<eblocks, 256>>>(erow, ecol, ew, fil_s, fil_t, csr_s, csr_t, E);

    // ---- input projections ----
    int gblocks = (M + 127) / 128;
    gemm_input_kernel<<<gblocks, 256>>>(fsrc, W_src, b_src, w_s, cs, fs, M);
    gemm_input_kernel<<<gblocks, 256>>>(ftgt, W_tgt, b_tgt, w_t, ct, ft, M);

    // ---- hops ----
    int sblocks = (M * 32 + 255) / 256;   // warp per node
    for (int h = 1; h <= HOPS; h++) {
        spmm_kernel<<<sblocks, 256>>>(rp_s, csr_s, cs, ns, fs, w_s, h, M);
        spmm_kernel<<<sblocks, 256>>>(rp_t, csr_t, ct, nt, ft, w_t, h, M);
        __half* tmp;
        tmp = cs; cs = ns; ns = tmp;
        tmp = ct; ct = nt; nt = tmp;
    }

    // ---- output projection ----
    gemm_out_kernel<<<(M + 63) / 64, 256>>>(fs, ft, W_nd, b_nd, out, M);
}

// round 4
// speedup vs baseline: 4.2150x; 1.2921x over previous
#include <cuda_runtime.h>
#include <cuda_fp16.h>
#include <cstddef>
#include <cstdint>

#define NN    100000
#define NEDGE 3200000
#define FEAT  256
#define HID   128
#define NOUT  64
#define HOPS  3

// fp16 hop buffers: curr_s, next_s, curr_t, next_t
__device__ __half g_hbuf[4][(size_t)NN * HID];
// fp32 feat accumulators: feat_s, feat_t
__device__ float  g_feat[2][(size_t)NN * HID];
__device__ int    g_deg[2][NN];
__device__ int    g_rowptr[2][NN + 1];
__device__ int    g_fill[2][NN];
__device__ int    g_bsum[2][128];
__device__ int2   g_csr[2][NEDGE];

// ======================= CSR build =======================
__global__ __launch_bounds__(256)
void hist_kernel(const int* __restrict__ erow, const int* __restrict__ ecol,
                 int* __restrict__ deg_s, int* __restrict__ deg_t, int E) {
    int e = blockIdx.x * blockDim.x + threadIdx.x;
    if (e < E) {
        atomicAdd(&deg_s[erow[e]], 1);
        atomicAdd(&deg_t[ecol[e]], 1);
    }
}

__global__ __launch_bounds__(1024)
void scan_chunk(const int* __restrict__ in, int* __restrict__ out,
                int* __restrict__ bsum, int n) {
    __shared__ int sh[1024];
    int t = threadIdx.x;
    int g = blockIdx.x * 1024 + t;
    int v = (g < n) ? in[g] : 0;
    sh[t] = v;
    __syncthreads();
    #pragma unroll
    for (int off = 1; off < 1024; off <<= 1) {
        int x = (t >= off) ? sh[t - off] : 0;
        __syncthreads();
        sh[t] += x;
        __syncthreads();
    }
    if (g < n) out[g] = sh[t] - v;         // exclusive within chunk
    if (t == 1023) bsum[blockIdx.x] = sh[1023];
}

__global__ void scan_block_sums2(int* bsum_s, int* bsum_t, int nb) {
    if (threadIdx.x == 0) {
        int* b = blockIdx.x ? bsum_t : bsum_s;
        int s = 0;
        for (int i = 0; i < nb; i++) { int v = b[i]; b[i] = s; s += v; }
    }
}

// both directions in one launch (blockIdx.y selects)
__global__ __launch_bounds__(256)
void scan_finalize2(int* __restrict__ rp_s, const int* __restrict__ bs_s,
                    int* __restrict__ fil_s,
                    int* __restrict__ rp_t, const int* __restrict__ bs_t,
                    int* __restrict__ fil_t, int n, int total) {
    int g = blockIdx.x * blockDim.x + threadIdx.x;
    int* rowptr = blockIdx.y ? rp_t : rp_s;
    const int* boff = blockIdx.y ? bs_t : bs_s;
    int* fill = blockIdx.y ? fil_t : fil_s;
    if (g < n) {
        int v = rowptr[g] + boff[g >> 10];
        rowptr[g] = v;
        fill[g] = v;
    }
    if (g == n) rowptr[n] = total;
}

__global__ __launch_bounds__(256)
void scatter_kernel(const int* __restrict__ erow, const int* __restrict__ ecol,
                    const float* __restrict__ ew,
                    int* __restrict__ fill_s, int* __restrict__ fill_t,
                    int2* __restrict__ csr_s, int2* __restrict__ csr_t, int E) {
    int e = blockIdx.x * blockDim.x + threadIdx.x;
    if (e >= E) return;
    int r = erow[e];
    int c = ecol[e];
    int wb = __float_as_int(ew[e]);
    int ps = atomicAdd(&fill_s[r], 1);
    csr_s[ps] = make_int2(c, wb);
    int pt = atomicAdd(&fill_t[c], 1);
    csr_t[pt] = make_int2(r, wb);
}

// ======================= SPMM (fp16 gather, fp32 accumulate) ================
__global__ __launch_bounds__(256)
void spmm_kernel(const int* __restrict__ rowptr, const int2* __restrict__ csr,
                 const __half* __restrict__ x, __half* __restrict__ next,
                 float* __restrict__ feat, const float* __restrict__ whop,
                 int h, int n) {
    int lane = threadIdx.x & 31;
    int node = (int)((blockIdx.x * blockDim.x + threadIdx.x) >> 5);
    if (node >= n) return;
    int beg = rowptr[node];
    int end = rowptr[node + 1];
    float4 acc = make_float4(0.f, 0.f, 0.f, 0.f);

    int p = beg;
    for (; p + 32 <= end; p += 32) {
        int2 ed = csr[p + lane];
        #pragma unroll
        for (int j = 0; j < 32; j++) {
            int   c  = __shfl_sync(0xffffffffu, ed.x, j);
            float wv = __int_as_float(__shfl_sync(0xffffffffu, ed.y, j));
            __half2 h2[2];
            *(uint2*)h2 = *((const uint2*)(x + (size_t)c * HID) + lane);
            float2 v0 = __half22float2(h2[0]);
            float2 v1 = __half22float2(h2[1]);
            acc.x += wv * v0.x; acc.y += wv * v0.y;
            acc.z += wv * v1.x; acc.w += wv * v1.y;
        }
    }
    int rem = end - p;
    if (rem > 0) {
        int2 ed = (lane < rem) ? csr[p + lane] : make_int2(0, 0);
        for (int j = 0; j < rem; j++) {
            int   c  = __shfl_sync(0xffffffffu, ed.x, j);
            float wv = __int_as_float(__shfl_sync(0xffffffffu, ed.y, j));
            __half2 h2[2];
            *(uint2*)h2 = *((const uint2*)(x + (size_t)c * HID) + lane);
            float2 v0 = __half22float2(h2[0]);
            float2 v1 = __half22float2(h2[1]);
            acc.x += wv * v0.x; acc.y += wv * v0.y;
            acc.z += wv * v1.x; acc.w += wv * v1.y;
        }
    }

    __half2 o2[2];
    o2[0] = __floats2half2_rn(acc.x, acc.y);
    o2[1] = __floats2half2_rn(acc.z, acc.w);
    *((uint2*)(next + (size_t)node * HID) + lane) = *(uint2*)o2;

    float wh = whop[h];
    float4* fp = (float4*)(feat + (size_t)node * HID) + lane;
    float4 f = *fp;
    f.x += wh * acc.x; f.y += wh * acc.y;
    f.z += wh * acc.z; f.w += wh * acc.w;
    *fp = f;
}

// ======================= input GEMM via tensor cores ========================
// x = A @ W + b ; curr = fp16(x) ; feat = w0 * x (fp32)
// A:[M,256] fp32 -> fp16, W:[256,128] fp32 -> fp16, mma m16n8k16 fp32 accum.
// Block: 128 rows x 128 cols, 8 warps (4x2), warp tile 32x64.

__device__ __forceinline__ uint32_t smem_u32(const void* p) {
    return (uint32_t)__cvta_generic_to_shared(p);
}
__device__ __forceinline__ void ldsm_x4(uint32_t* r, uint32_t addr) {
    asm volatile("ldmatrix.sync.aligned.m8n8.x4.shared.b16 {%0,%1,%2,%3}, [%4];"
                 : "=r"(r[0]), "=r"(r[1]), "=r"(r[2]), "=r"(r[3]) : "r"(addr));
}
__device__ __forceinline__ void ldsm_x4_t(uint32_t* r, uint32_t addr) {
    asm volatile("ldmatrix.sync.aligned.m8n8.x4.trans.shared.b16 {%0,%1,%2,%3}, [%4];"
                 : "=r"(r[0]), "=r"(r[1]), "=r"(r[2]), "=r"(r[3]) : "r"(addr));
}
__device__ __forceinline__ void mma16816(float* c, const uint32_t* a,
                                         uint32_t b0, uint32_t b1) {
    asm volatile("mma.sync.aligned.m16n8k16.row.col.f32.f16.f16.f32 "
                 "{%0,%1,%2,%3}, {%4,%5,%6,%7}, {%8,%9}, {%0,%1,%2,%3};"
                 : "+f"(c[0]), "+f"(c[1]), "+f"(c[2]), "+f"(c[3])
                 : "r"(a[0]), "r"(a[1]), "r"(a[2]), "r"(a[3]), "r"(b0), "r"(b1));
}

#define A_STRIDE 40   // halves per row (32 + 8 pad)
#define W_STRIDE 136  // halves per row (128 + 8 pad)

__global__ __launch_bounds__(256)
void gemm_input_mma(const float* __restrict__ A, const float* __restrict__ W,
                    const float* __restrict__ bias, const float* __restrict__ whop,
                    __half* __restrict__ curr, float* __restrict__ feat, int M) {
    __shared__ __half Ah[128 * A_STRIDE];
    __shared__ __half Wh[32 * W_STRIDE];
    int tid = threadIdx.x;
    int lane = tid & 31;
    int warp = tid >> 5;
    int wm = warp >> 1;     // 0..3 -> m offset wm*32
    int wn = warp & 1;      // 0..1 -> n offset wn*64
    int row0 = blockIdx.x * 128;

    float acc[2][8][4];
    #pragma unroll
    for (int i = 0; i < 2; i++)
        #pragma unroll
        for (int j = 0; j < 8; j++)
            #pragma unroll
            for (int k = 0; k < 4; k++) acc[i][j][k] = 0.f;

    for (int k0 = 0; k0 < FEAT; k0 += 32) {
        // A tile: 128 rows x 32 cols (1024 float4, 4 per thread)
        #pragma unroll
        for (int i = 0; i < 4; i++) {
            int f = tid + i * 256;
            int r = f >> 3;
            int cg = (f & 7) * 4;
            float4 v = make_float4(0.f, 0.f, 0.f, 0.f);
            if (row0 + r < M)
                v = *(const float4*)(A + (size_t)(row0 + r) * FEAT + k0 + cg);
            __half2 h0 = __floats2half2_rn(v.x, v.y);
            __half2 h1 = __floats2half2_rn(v.z, v.w);
            *(uint2*)&Ah[r * A_STRIDE + cg] = make_uint2(*(uint32_t*)&h0, *(uint32_t*)&h1);
        }
        // W tile: 32 rows x 128 cols (1024 float4, 4 per thread)
        #pragma unroll
        for (int i = 0; i < 4; i++) {
            int f = tid + i * 256;
            int r = f >> 5;
            int cg = (f & 31) * 4;
            float4 v = *(const float4*)(W + (size_t)(k0 + r) * HID + cg);
            __half2 h0 = __floats2half2_rn(v.x, v.y);
            __half2 h1 = __floats2half2_rn(v.z, v.w);
            *(uint2*)&Wh[r * W_STRIDE + cg] = make_uint2(*(uint32_t*)&h0, *(uint32_t*)&h1);
        }
        __syncthreads();

        #pragma unroll
        for (int ks = 0; ks < 32; ks += 16) {
            uint32_t aF[2][4];
            #pragma unroll
            for (int mt = 0; mt < 2; mt++) {
                int r = wm * 32 + mt * 16 + (lane & 15);
                int c = ks + ((lane >> 4) << 3);
                ldsm_x4(aF[mt], smem_u32(&Ah[r * A_STRIDE + c]));
            }
            uint32_t bF[4][4];
            #pragma unroll
            for (int ng = 0; ng < 4; ng++) {
                int r = ks + ((lane >> 4) << 3) + (lane & 7);
                int c = wn * 64 + ng * 16 + (((lane >> 3) & 1) << 3);
                ldsm_x4_t(bF[ng], smem_u32(&Wh[r * W_STRIDE + c]));
            }
            #pragma unroll
            for (int mt = 0; mt < 2; mt++)
                #pragma unroll
                for (int nt = 0; nt < 8; nt++) {
                    int ng = nt >> 1, sel = nt & 1;
                    mma16816(acc[mt][nt], aF[mt], bF[ng][sel], bF[ng][sel + 2]);
                }
        }
        __syncthreads();
    }

    // epilogue
    float w0 = whop[0];
    #pragma unroll
    for (int mt = 0; mt < 2; mt++) {
        int r_ = row0 + wm * 32 + mt * 16 + (lane >> 2);
        #pragma unroll
        for (int nt = 0; nt < 8; nt++) {
            int c_ = wn * 64 + nt * 8 + (lane & 3) * 2;
            float b0 = __ldg(bias + c_);
            float b1 = __ldg(bias + c_ + 1);
            if (r_ < M) {
                float v0 = acc[mt][nt][0] + b0;
                float v1 = acc[mt][nt][1] + b1;
                __half2 hv = __floats2half2_rn(v0, v1);
                *(__half2*)(curr + (size_t)r_ * HID + c_) = hv;
                *(float2*)(feat + (size_t)r_ * HID + c_) = make_float2(w0 * v0, w0 * v1);
            }
            if (r_ + 8 < M) {
                float v0 = acc[mt][nt][2] + b0;
                float v1 = acc[mt][nt][3] + b1;
                __half2 hv = __floats2half2_rn(v0, v1);
                *(__half2*)(curr + (size_t)(r_ + 8) * HID + c_) = hv;
                *(float2*)(feat + (size_t)(r_ + 8) * HID + c_) = make_float2(w0 * v0, w0 * v1);
            }
        }
    }
}

// ======================= output GEMM: out = [fs|ft] @ W_node + b ============
__global__ __launch_bounds__(256)
void gemm_out_kernel(const float* __restrict__ fs, const float* __restrict__ ft,
                     const float* __restrict__ Wn, const float* __restrict__ bn,
                     float* __restrict__ out, int M) {
    __shared__ float As[16][64];
    __shared__ float Bs[16][64];
    int tid = threadIdx.x;
    int tx = tid & 15;
    int ty = tid >> 4;
    int row0 = blockIdx.x * 64;

    float acc[4][4];
    #pragma unroll
    for (int i = 0; i < 4; i++)
        #pragma unroll
        for (int j = 0; j < 4; j++) acc[i][j] = 0.f;

    int arow = tid >> 2;
    int acol = (tid & 3) * 4;

    for (int k0 = 0; k0 < 2 * HID; k0 += 16) {
        const float* A = (k0 < HID) ? fs : ft;
        int kc = k0 & (HID - 1);
        float4 av = make_float4(0.f, 0.f, 0.f, 0.f);
        int gr = row0 + arow;
        if (gr < M) av = *(const float4*)(A + (size_t)gr * HID + kc + acol);
        As[acol + 0][arow] = av.x;
        As[acol + 1][arow] = av.y;
        As[acol + 2][arow] = av.z;
        As[acol + 3][arow] = av.w;
        {
            int brow = tid >> 4;
            int bcol = (tid & 15) * 4;
            *(float4*)&Bs[brow][bcol] =
                *(const float4*)(Wn + (size_t)(k0 + brow) * NOUT + bcol);
        }
        __syncthreads();
        #pragma unroll
        for (int kk = 0; kk < 16; kk++) {
            float a[4], b[4];
            *(float4*)&a[0] = *(const float4*)&As[kk][ty * 4];
            *(float4*)&b[0] = *(const float4*)&Bs[kk][tx * 4];
            #pragma unroll
            for (int i = 0; i < 4; i++)
                #pragma unroll
                for (int j = 0; j < 4; j++) acc[i][j] += a[i] * b[j];
        }
        __syncthreads();
    }

    float4 bb = *(const float4*)(bn + tx * 4);
    #pragma unroll
    for (int i = 0; i < 4; i++) {
        int r = row0 + ty * 4 + i;
        if (r < M) {
            float4 v;
            v.x = acc[i][0] + bb.x;
            v.y = acc[i][1] + bb.y;
            v.z = acc[i][2] + bb.z;
            v.w = acc[i][3] + bb.w;
            *(float4*)(out + (size_t)r * NOUT + tx * 4) = v;
        }
    }
}

// ===========================================================================
extern "C" void kernel_launch(void* const* d_in, const int* in_sizes, int n_in,
                              void* d_out, int out_size) {
    const float* fsrc  = (const float*)d_in[0];
    const float* ftgt  = (const float*)d_in[1];
    const int*   erow  = (const int*)d_in[2];
    const int*   ecol  = (const int*)d_in[3];
    const float* ew    = (const float*)d_in[4];
    const float* W_src = (const float*)d_in[5];
    const float* b_src = (const float*)d_in[6];
    const float* W_tgt = (const float*)d_in[7];
    const float* b_tgt = (const float*)d_in[8];
    const float* w_s   = (const float*)d_in[9];
    const float* w_t   = (const float*)d_in[10];
    const float* W_nd  = (const float*)d_in[11];
    const float* b_nd  = (const float*)d_in[12];
    float* out = (float*)d_out;

    int M = in_sizes[0] / FEAT;
    int E = in_sizes[2];

    __half* hbase;  cudaGetSymbolAddress((void**)&hbase, g_hbuf);
    float*  fbase;  cudaGetSymbolAddress((void**)&fbase, g_feat);
    int*    deg;    cudaGetSymbolAddress((void**)&deg, g_deg);
    int*    rowptr; cudaGetSymbolAddress((void**)&rowptr, g_rowptr);
    int*    fill;   cudaGetSymbolAddress((void**)&fill, g_fill);
    int*    bsum;   cudaGetSymbolAddress((void**)&bsum, g_bsum);
    int2*   csr;    cudaGetSymbolAddress((void**)&csr, g_csr);

    size_t cap = (size_t)NN * HID;
    __half* cs = hbase + 0 * cap;
    __half* ns = hbase + 1 * cap;
    __half* ct = hbase + 2 * cap;
    __half* nt = hbase + 3 * cap;
    float*  fs = fbase + 0 * cap;
    float*  ft = fbase + 1 * cap;

    int* deg_s = deg;            int* deg_t = deg + NN;
    int* rp_s  = rowptr;         int* rp_t  = rowptr + (NN + 1);
    int* fil_s = fill;           int* fil_t = fill + NN;
    int* bs_s  = bsum;           int* bs_t  = bsum + 128;
    int2* csr_s = csr;           int2* csr_t = csr + NEDGE;

    int eblocks = (E + 255) / 256;
    int nchunks = (M + 1023) / 1024;

    // ---- CSR build (both directions) ----
    cudaMemsetAsync(deg_s, 0, 2 * NN * sizeof(int));
    hist_kernel<<<eblocks, 256>>>(erow, ecol, deg_s, deg_t, E);
    scan_chunk<<<nchunks, 1024>>>(deg_s, rp_s, bs_s, M);
    scan_chunk<<<nchunks, 1024>>>(deg_t, rp_t, bs_t, M);
    scan_block_sums2<<<2, 32>>>(bs_s, bs_t, nchunks);
    {
        dim3 g((M + 256) / 256, 2);
        scan_finalize2<<<g, 256>>>(rp_s, bs_s, fil_s, rp_t, bs_t, fil_t, M, E);
    }
    scatter_kernel<<<eblocks, 256>>>(erow, ecol, ew, fil_s, fil_t, csr_s, csr_t, E);

    // ---- input projections (tensor cores) ----
    int gblocks = (M + 127) / 128;
    gemm_input_mma<<<gblocks, 256>>>(fsrc, W_src, b_src, w_s, cs, fs, M);
    gemm_input_mma<<<gblocks, 256>>>(ftgt, W_tgt, b_tgt, w_t, ct, ft, M);

    // ---- hops ----
    int sblocks = (M * 32 + 255) / 256;   // warp per node
    for (int h = 1; h <= HOPS; h++) {
        spmm_kernel<<<sblocks, 256>>>(rp_s, csr_s, cs, ns, fs, w_s, h, M);
        spmm_kernel<<<sblocks, 256>>>(rp_t, csr_t, ct, nt, ft, w_t, h, M);
        __half* tmp;
        tmp = cs; cs = ns; ns = tmp;
        tmp = ct; ct = nt; nt = tmp;
    }

    // ---- output projection ----
    gemm_out_kernel<<<(M + 63) / 64, 256>>>(fs, ft, W_nd, b_nd, out, M);
}

// round 5
// speedup vs baseline: 4.6394x; 1.1007x over previous
#include <cuda_runtime.h>
#include <cuda_fp16.h>
#include <cstddef>
#include <cstdint>

#define NN    100000
#define NEDGE 3200000
#define FEAT  256
#define HID   128
#define NOUT  64
#define HOPS  3
#define CAP   ((size_t)NN * HID)

// 8 fp16 hop buffers: s-dir h0..h3, t-dir h0..h3
__device__ __half g_hbuf[8][CAP];
__device__ int    g_deg[2][NN];
__device__ int    g_rowptr[2][NN + 1];
__device__ int    g_fill[2][NN];
__device__ int    g_bsum[2][128];
__device__ int2   g_csr[2][NEDGE];

// ======================= CSR build =======================
__global__ __launch_bounds__(256)
void hist_kernel(const int* __restrict__ erow, const int* __restrict__ ecol,
                 int* __restrict__ deg_s, int* __restrict__ deg_t, int E) {
    int e = blockIdx.x * blockDim.x + threadIdx.x;
    if (e < E) {
        atomicAdd(&deg_s[erow[e]], 1);
        atomicAdd(&deg_t[ecol[e]], 1);
    }
}

__global__ __launch_bounds__(1024)
void scan_chunk(const int* __restrict__ in, int* __restrict__ out,
                int* __restrict__ bsum, int n) {
    __shared__ int sh[1024];
    int t = threadIdx.x;
    int g = blockIdx.x * 1024 + t;
    int v = (g < n) ? in[g] : 0;
    sh[t] = v;
    __syncthreads();
    #pragma unroll
    for (int off = 1; off < 1024; off <<= 1) {
        int x = (t >= off) ? sh[t - off] : 0;
        __syncthreads();
        sh[t] += x;
        __syncthreads();
    }
    if (g < n) out[g] = sh[t] - v;         // exclusive within chunk
    if (t == 1023) bsum[blockIdx.x] = sh[1023];
}

__global__ void scan_block_sums2(int* bsum_s, int* bsum_t, int nb) {
    if (threadIdx.x == 0) {
        int* b = blockIdx.x ? bsum_t : bsum_s;
        int s = 0;
        for (int i = 0; i < nb; i++) { int v = b[i]; b[i] = s; s += v; }
    }
}

__global__ __launch_bounds__(256)
void scan_finalize2(int* __restrict__ rp_s, const int* __restrict__ bs_s,
                    int* __restrict__ fil_s,
                    int* __restrict__ rp_t, const int* __restrict__ bs_t,
                    int* __restrict__ fil_t, int n, int total) {
    int g = blockIdx.x * blockDim.x + threadIdx.x;
    int* rowptr = blockIdx.y ? rp_t : rp_s;
    const int* boff = blockIdx.y ? bs_t : bs_s;
    int* fill = blockIdx.y ? fil_t : fil_s;
    if (g < n) {
        int v = rowptr[g] + boff[g >> 10];
        rowptr[g] = v;
        fill[g] = v;
    }
    if (g == n) rowptr[n] = total;
}

__global__ __launch_bounds__(256)
void scatter_kernel(const int* __restrict__ erow, const int* __restrict__ ecol,
                    const float* __restrict__ ew,
                    int* __restrict__ fill_s, int* __restrict__ fill_t,
                    int2* __restrict__ csr_s, int2* __restrict__ csr_t, int E) {
    int e = blockIdx.x * blockDim.x + threadIdx.x;
    if (e >= E) return;
    int r = erow[e];
    int c = ecol[e];
    int wb = __float_as_int(ew[e]);
    int ps = atomicAdd(&fill_s[r], 1);
    csr_s[ps] = make_int2(c, wb);
    int pt = atomicAdd(&fill_t[c], 1);
    csr_t[pt] = make_int2(r, wb);
}

// ======================= SPMM (fp16 gather, fp32 accumulate) ================
// both directions in one launch; next[i] = fp16( sum_e w_e * x[nbr_e] )
__global__ __launch_bounds__(256)
void spmm2_kernel(const int* __restrict__ rp_s, const int* __restrict__ rp_t,
                  const int2* __restrict__ csr_s, const int2* __restrict__ csr_t,
                  __half* __restrict__ hb, int h, int n) {
    int dir = blockIdx.y;
    const int* rowptr = dir ? rp_t : rp_s;
    const int2* csr = dir ? csr_t : csr_s;
    const __half* x = hb + (size_t)(dir * 4 + h - 1) * CAP;
    __half* next = hb + (size_t)(dir * 4 + h) * CAP;

    int lane = threadIdx.x & 31;
    int node = (int)((blockIdx.x * blockDim.x + threadIdx.x) >> 5);
    if (node >= n) return;
    int beg = rowptr[node];
    int end = rowptr[node + 1];
    float4 acc = make_float4(0.f, 0.f, 0.f, 0.f);

    int p = beg;
    for (; p + 32 <= end; p += 32) {
        int2 ed = csr[p + lane];
        #pragma unroll
        for (int j = 0; j < 32; j++) {
            int   c  = __shfl_sync(0xffffffffu, ed.x, j);
            float wv = __int_as_float(__shfl_sync(0xffffffffu, ed.y, j));
            __half2 h2[2];
            *(uint2*)h2 = *((const uint2*)(x + (size_t)c * HID) + lane);
            float2 v0 = __half22float2(h2[0]);
            float2 v1 = __half22float2(h2[1]);
            acc.x += wv * v0.x; acc.y += wv * v0.y;
            acc.z += wv * v1.x; acc.w += wv * v1.y;
        }
    }
    int rem = end - p;
    if (rem > 0) {
        int2 ed = (lane < rem) ? csr[p + lane] : make_int2(0, 0);
        for (int j = 0; j < rem; j++) {
            int   c  = __shfl_sync(0xffffffffu, ed.x, j);
            float wv = __int_as_float(__shfl_sync(0xffffffffu, ed.y, j));
            __half2 h2[2];
            *(uint2*)h2 = *((const uint2*)(x + (size_t)c * HID) + lane);
            float2 v0 = __half22float2(h2[0]);
            float2 v1 = __half22float2(h2[1]);
            acc.x += wv * v0.x; acc.y += wv * v0.y;
            acc.z += wv * v1.x; acc.w += wv * v1.y;
        }
    }

    __half2 o2[2];
    o2[0] = __floats2half2_rn(acc.x, acc.y);
    o2[1] = __floats2half2_rn(acc.z, acc.w);
    *((uint2*)(next + (size_t)node * HID) + lane) = *(uint2*)o2;
}

// ======================= tensor-core helpers ========================
__device__ __forceinline__ uint32_t smem_u32(const void* p) {
    return (uint32_t)__cvta_generic_to_shared(p);
}
__device__ __forceinline__ void ldsm_x4(uint32_t* r, uint32_t addr) {
    asm volatile("ldmatrix.sync.aligned.m8n8.x4.shared.b16 {%0,%1,%2,%3}, [%4];"
                 : "=r"(r[0]), "=r"(r[1]), "=r"(r[2]), "=r"(r[3]) : "r"(addr));
}
__device__ __forceinline__ void ldsm_x4_t(uint32_t* r, uint32_t addr) {
    asm volatile("ldmatrix.sync.aligned.m8n8.x4.trans.shared.b16 {%0,%1,%2,%3}, [%4];"
                 : "=r"(r[0]), "=r"(r[1]), "=r"(r[2]), "=r"(r[3]) : "r"(addr));
}
__device__ __forceinline__ void mma16816(float* c, const uint32_t* a,
                                         uint32_t b0, uint32_t b1) {
    asm volatile("mma.sync.aligned.m16n8k16.row.col.f32.f16.f16.f32 "
                 "{%0,%1,%2,%3}, {%4,%5,%6,%7}, {%8,%9}, {%0,%1,%2,%3};"
                 : "+f"(c[0]), "+f"(c[1]), "+f"(c[2]), "+f"(c[3])
                 : "r"(a[0]), "r"(a[1]), "r"(a[2]), "r"(a[3]), "r"(b0), "r"(b1));
}

#define A_STRIDE 40   // halves per row (32 + 8 pad)
#define W_STRIDE 136  // halves per row (128 + 8 pad)
#define W2_STRIDE 72  // halves per row (64 + 8 pad)

// ======================= input GEMM via tensor cores ========================
// h0 = fp16(A @ W + b); both projections in one launch (blockIdx.y)
__global__ __launch_bounds__(256)
void gemm_input2_mma(const float* __restrict__ A0, const float* __restrict__ W0,
                     const float* __restrict__ bias0,
                     const float* __restrict__ A1, const float* __restrict__ W1,
                     const float* __restrict__ bias1,
                     __half* __restrict__ hb, int M) {
    const float* A    = blockIdx.y ? A1 : A0;
    const float* W    = blockIdx.y ? W1 : W0;
    const float* bias = blockIdx.y ? bias1 : bias0;
    __half* curr = hb + (size_t)(blockIdx.y * 4) * CAP;

    __shared__ __half Ah[128 * A_STRIDE];
    __shared__ __half Wh[32 * W_STRIDE];
    int tid = threadIdx.x;
    int lane = tid & 31;
    int warp = tid >> 5;
    int wm = warp >> 1;
    int wn = warp & 1;
    int row0 = blockIdx.x * 128;

    float acc[2][8][4];
    #pragma unroll
    for (int i = 0; i < 2; i++)
        #pragma unroll
        for (int j = 0; j < 8; j++)
            #pragma unroll
            for (int k = 0; k < 4; k++) acc[i][j][k] = 0.f;

    for (int k0 = 0; k0 < FEAT; k0 += 32) {
        #pragma unroll
        for (int i = 0; i < 4; i++) {
            int f = tid + i * 256;
            int r = f >> 3;
            int cg = (f & 7) * 4;
            float4 v = make_float4(0.f, 0.f, 0.f, 0.f);
            if (row0 + r < M)
                v = *(const float4*)(A + (size_t)(row0 + r) * FEAT + k0 + cg);
            __half2 h0 = __floats2half2_rn(v.x, v.y);
            __half2 h1 = __floats2half2_rn(v.z, v.w);
            *(uint2*)&Ah[r * A_STRIDE + cg] = make_uint2(*(uint32_t*)&h0, *(uint32_t*)&h1);
        }
        #pragma unroll
        for (int i = 0; i < 4; i++) {
            int f = tid + i * 256;
            int r = f >> 5;
            int cg = (f & 31) * 4;
            float4 v = *(const float4*)(W + (size_t)(k0 + r) * HID + cg);
            __half2 h0 = __floats2half2_rn(v.x, v.y);
            __half2 h1 = __floats2half2_rn(v.z, v.w);
            *(uint2*)&Wh[r * W_STRIDE + cg] = make_uint2(*(uint32_t*)&h0, *(uint32_t*)&h1);
        }
        __syncthreads();

        #pragma unroll
        for (int ks = 0; ks < 32; ks += 16) {
            uint32_t aF[2][4];
            #pragma unroll
            for (int mt = 0; mt < 2; mt++) {
                int r = wm * 32 + mt * 16 + (lane & 15);
                int c = ks + ((lane >> 4) << 3);
                ldsm_x4(aF[mt], smem_u32(&Ah[r * A_STRIDE + c]));
            }
            uint32_t bF[4][4];
            #pragma unroll
            for (int ng = 0; ng < 4; ng++) {
                int r = ks + ((lane >> 4) << 3) + (lane & 7);
                int c = wn * 64 + ng * 16 + (((lane >> 3) & 1) << 3);
                ldsm_x4_t(bF[ng], smem_u32(&Wh[r * W_STRIDE + c]));
            }
            #pragma unroll
            for (int mt = 0; mt < 2; mt++)
                #pragma unroll
                for (int nt = 0; nt < 8; nt++) {
                    int ng = nt >> 1, sel = nt & 1;
                    mma16816(acc[mt][nt], aF[mt], bF[ng][sel], bF[ng][sel + 2]);
                }
        }
        __syncthreads();
    }

    #pragma unroll
    for (int mt = 0; mt < 2; mt++) {
        int r_ = row0 + wm * 32 + mt * 16 + (lane >> 2);
        #pragma unroll
        for (int nt = 0; nt < 8; nt++) {
            int c_ = wn * 64 + nt * 8 + (lane & 3) * 2;
            float b0 = __ldg(bias + c_);
            float b1 = __ldg(bias + c_ + 1);
            if (r_ < M) {
                __half2 hv = __floats2half2_rn(acc[mt][nt][0] + b0, acc[mt][nt][1] + b1);
                *(__half2*)(curr + (size_t)r_ * HID + c_) = hv;
            }
            if (r_ + 8 < M) {
                __half2 hv = __floats2half2_rn(acc[mt][nt][2] + b0, acc[mt][nt][3] + b1);
                *(__half2*)(curr + (size_t)(r_ + 8) * HID + c_) = hv;
            }
        }
    }
}

// ======================= output GEMM (tensor cores, fused hop combine) ======
// A_cat[r, k] = sum_h w_dir[h] * hb[dir*4+h][r, k mod 128], dir = k/128
// out = A_cat @ Wn + bn.  Block 128x64, 8 warps (4x2), warp tile 32x32.
__global__ __launch_bounds__(256)
void gemm_out_mma(const __half* __restrict__ hb,
                  const float* __restrict__ w_s, const float* __restrict__ w_t,
                  const float* __restrict__ Wn, const float* __restrict__ bn,
                  float* __restrict__ out, int M) {
    __shared__ __half Ah[128 * A_STRIDE];
    __shared__ __half Wh[32 * W2_STRIDE];
    int tid = threadIdx.x;
    int lane = tid & 31;
    int warp = tid >> 5;
    int wm = warp >> 1;     // 0..3 -> m offset wm*32
    int wn = warp & 1;      // 0..1 -> n offset wn*32
    int row0 = blockIdx.x * 128;

    float acc[2][4][4];
    #pragma unroll
    for (int i = 0; i < 2; i++)
        #pragma unroll
        for (int j = 0; j < 4; j++)
            #pragma unroll
            for (int k = 0; k < 4; k++) acc[i][j][k] = 0.f;

    float ws0 = __ldg(w_s + 0), ws1 = __ldg(w_s + 1), ws2 = __ldg(w_s + 2), ws3 = __ldg(w_s + 3);
    float wt0 = __ldg(w_t + 0), wt1 = __ldg(w_t + 1), wt2 = __ldg(w_t + 2), wt3 = __ldg(w_t + 3);

    for (int k0 = 0; k0 < 2 * HID; k0 += 32) {
        int dir = (k0 >= HID);
        const __half* hd = hb + (size_t)(dir * 4) * CAP;
        float w0 = dir ? wt0 : ws0, w1 = dir ? wt1 : ws1;
        float w2 = dir ? wt2 : ws2, w3 = dir ? wt3 : ws3;
        int kc0 = k0 & (HID - 1);

        // A tile: 128 rows x 32 cols, weighted sum of 4 hop buffers
        #pragma unroll
        for (int i = 0; i < 2; i++) {
            int f = tid + i * 256;        // 0..511
            int r = f >> 2;               // 0..127
            int kg = (f & 3) * 8;         // 0,8,16,24
            float o[8];
            #pragma unroll
            for (int j = 0; j < 8; j++) o[j] = 0.f;
            if (row0 + r < M) {
                size_t off = (size_t)(row0 + r) * HID + kc0 + kg;
                #pragma unroll
                for (int h = 0; h < 4; h++) {
                    float wh = (h == 0) ? w0 : (h == 1) ? w1 : (h == 2) ? w2 : w3;
                    __half2 hv[4];
                    *(uint4*)hv = *(const uint4*)(hd + h * CAP + off);
                    #pragma unroll
                    for (int j = 0; j < 4; j++) {
                        float2 v = __half22float2(hv[j]);
                        o[2 * j]     += wh * v.x;
                        o[2 * j + 1] += wh * v.y;
                    }
                }
            }
            __half2 oh[4];
            #pragma unroll
            for (int j = 0; j < 4; j++) oh[j] = __floats2half2_rn(o[2 * j], o[2 * j + 1]);
            *(uint4*)&Ah[r * A_STRIDE + kg] = *(uint4*)oh;
        }
        // B tile: 32 rows x 64 cols fp32 -> fp16 (512 float4, 2 per thread)
        #pragma unroll
        for (int i = 0; i < 2; i++) {
            int f = tid + i * 256;
            int r = f >> 4;
            int cg = (f & 15) * 4;
            float4 v = *(const float4*)(Wn + (size_t)(k0 + r) * NOUT + cg);
            __half2 h0 = __floats2half2_rn(v.x, v.y);
            __half2 h1 = __floats2half2_rn(v.z, v.w);
            *(uint2*)&Wh[r * W2_STRIDE + cg] = make_uint2(*(uint32_t*)&h0, *(uint32_t*)&h1);
        }
        __syncthreads();

        #pragma unroll
        for (int ks = 0; ks < 32; ks += 16) {
            uint32_t aF[2][4];
            #pragma unroll
            for (int mt = 0; mt < 2; mt++) {
                int r = wm * 32 + mt * 16 + (lane & 15);
                int c = ks + ((lane >> 4) << 3);
                ldsm_x4(aF[mt], smem_u32(&Ah[r * A_STRIDE + c]));
            }
            uint32_t bF[2][4];
            #pragma unroll
            for (int ng = 0; ng < 2; ng++) {
                int r = ks + ((lane >> 4) << 3) + (lane & 7);
                int c = wn * 32 + ng * 16 + (((lane >> 3) & 1) << 3);
                ldsm_x4_t(bF[ng], smem_u32(&Wh[r * W2_STRIDE + c]));
            }
            #pragma unroll
            for (int mt = 0; mt < 2; mt++)
                #pragma unroll
                for (int nt = 0; nt < 4; nt++) {
                    int ng = nt >> 1, sel = nt & 1;
                    mma16816(acc[mt][nt], aF[mt], bF[ng][sel], bF[ng][sel + 2]);
                }
        }
        __syncthreads();
    }

    #pragma unroll
    for (int mt = 0; mt < 2; mt++) {
        int r_ = row0 + wm * 32 + mt * 16 + (lane >> 2);
        #pragma unroll
        for (int nt = 0; nt < 4; nt++) {
            int c_ = wn * 32 + nt * 8 + (lane & 3) * 2;
            float b0 = __ldg(bn + c_);
            float b1 = __ldg(bn + c_ + 1);
            if (r_ < M)
                *(float2*)(out + (size_t)r_ * NOUT + c_) =
                    make_float2(acc[mt][nt][0] + b0, acc[mt][nt][1] + b1);
            if (r_ + 8 < M)
                *(float2*)(out + (size_t)(r_ + 8) * NOUT + c_) =
                    make_float2(acc[mt][nt][2] + b0, acc[mt][nt][3] + b1);
        }
    }
}

// ===========================================================================
extern "C" void kernel_launch(void* const* d_in, const int* in_sizes, int n_in,
                              void* d_out, int out_size) {
    const float* fsrc  = (const float*)d_in[0];
    const float* ftgt  = (const float*)d_in[1];
    const int*   erow  = (const int*)d_in[2];
    const int*   ecol  = (const int*)d_in[3];
    const float* ew    = (const float*)d_in[4];
    const float* W_src = (const float*)d_in[5];
    const float* b_src = (const float*)d_in[6];
    const float* W_tgt = (const float*)d_in[7];
    const float* b_tgt = (const float*)d_in[8];
    const float* w_s   = (const float*)d_in[9];
    const float* w_t   = (const float*)d_in[10];
    const float* W_nd  = (const float*)d_in[11];
    const float* b_nd  = (const float*)d_in[12];
    float* out = (float*)d_out;

    int M = in_sizes[0] / FEAT;
    int E = in_sizes[2];

    __half* hb;     cudaGetSymbolAddress((void**)&hb, g_hbuf);
    int*    deg;    cudaGetSymbolAddress((void**)&deg, g_deg);
    int*    rowptr; cudaGetSymbolAddress((void**)&rowptr, g_rowptr);
    int*    fill;   cudaGetSymbolAddress((void**)&fill, g_fill);
    int*    bsum;   cudaGetSymbolAddress((void**)&bsum, g_bsum);
    int2*   csr;    cudaGetSymbolAddress((void**)&csr, g_csr);

    int* deg_s = deg;            int* deg_t = deg + NN;
    int* rp_s  = rowptr;         int* rp_t  = rowptr + (NN + 1);
    int* fil_s = fill;           int* fil_t = fill + NN;
    int* bs_s  = bsum;           int* bs_t  = bsum + 128;
    int2* csr_s = csr;           int2* csr_t = csr + NEDGE;

    int eblocks = (E + 255) / 256;
    int nchunks = (M + 1023) / 1024;

    // ---- CSR build (both directions) ----
    cudaMemsetAsync(deg_s, 0, 2 * NN * sizeof(int));
    hist_kernel<<<eblocks, 256>>>(erow, ecol, deg_s, deg_t, E);
    scan_chunk<<<nchunks, 1024>>>(deg_s, rp_s, bs_s, M);
    scan_chunk<<<nchunks, 1024>>>(deg_t, rp_t, bs_t, M);
    scan_block_sums2<<<2, 32>>>(bs_s, bs_t, nchunks);
    {
        dim3 g((M + 256) / 256, 2);
        scan_finalize2<<<g, 256>>>(rp_s, bs_s, fil_s, rp_t, bs_t, fil_t, M, E);
    }
    scatter_kernel<<<eblocks, 256>>>(erow, ecol, ew, fil_s, fil_t, csr_s, csr_t, E);

    // ---- input projections (tensor cores, both in one launch) ----
    {
        dim3 g((M + 127) / 128, 2);
        gemm_input2_mma<<<g, 256>>>(fsrc, W_src, b_src, ftgt, W_tgt, b_tgt, hb, M);
    }

    // ---- hops (both directions per launch) ----
    {
        dim3 g((M * 32 + 255) / 256, 2);
        for (int h = 1; h <= HOPS; h++)
            spmm2_kernel<<<g, 256>>>(rp_s, rp_t, csr_s, csr_t, hb, h, M);
    }

    // ---- output projection (tensor cores, fused hop combine) ----
    gemm_out_mma<<<(M + 127) / 128, 256>>>(hb, w_s, w_t, W_nd, b_nd, out, M);
}